// round 6
// baseline (speedup 1.0000x reference)
#include <cuda_runtime.h>
#include <cstdint>
#include <cstddef>

#define NN   8192
#define FIN  256
#define FOUT 64
#define CAP2 128          // per-row neighbor list capacity (mean 32, 11+ sigma safe)
#define PROJ_BLOCKS 256
#define SCAN_BLOCKS 2048  // 2048*256 threads * 32 uint4 = 8192*8192/4

__device__ float g_fts[(size_t)NN * FOUT];
__device__ float g_f1[NN];
__device__ float g_f2[NN];
__device__ int   g_cnt[NN];            // zero-init at load; reset by agg_kernel
__device__ int   g_lst[(size_t)NN * CAP2];

__device__ __forceinline__ float lrelu(float v) { return fmaxf(v, 0.2f * v); }

__device__ __forceinline__ unsigned long long pack2(float lo, float hi) {
    unsigned long long r;
    asm("mov.b64 %0, {%1, %2};" : "=l"(r) : "f"(lo), "f"(hi));
    return r;
}
__device__ __forceinline__ unsigned long long ffma2(unsigned long long a,
                                                    unsigned long long b,
                                                    unsigned long long c) {
    unsigned long long d;
    asm("fma.rn.f32x2 %0, %1, %2, %3;" : "=l"(d) : "l"(a), "l"(b), "l"(c));
    return d;
}
__device__ __forceinline__ float2 unpack2(unsigned long long v) {
    float2 f;
    asm("mov.b64 {%0, %1}, %2;" : "=f"(f.x), "=f"(f.y) : "l"(v));
    return f;
}

// ---------------------------------------------------------------------------
// Fused kernel: blocks [0, PROJ_BLOCKS) = projection GEMM (FFMA-bound),
// blocks [PROJ_BLOCKS, +SCAN_BLOCKS) = pure-streaming adjacency compaction
// (DRAM-bound). Overlapped on the chip; proj vanishes from critical path.
// ---------------------------------------------------------------------------
__global__ void __launch_bounds__(256) fused_kernel(
    const float* __restrict__ x, const float* __restrict__ W,
    const float* __restrict__ a1, const float* __restrict__ b1,
    const float* __restrict__ a2, const float* __restrict__ b2,
    const float* __restrict__ adj)
{
    const int tid = threadIdx.x;

    if (blockIdx.x < PROJ_BLOCKS) {
        // ======== proj: 32 rows x 64 cols per block, K-chunks of 32 ========
        __shared__ __align__(16) float xsT[32 * 34];   // [k][row] pad 34
        __shared__ __align__(16) float Ws[32 * 64];    // [k][col]

        const int rowg = tid >> 4;       // 0..15 -> rows r0,r0+1
        const int colg = tid & 15;       // 0..15 -> 4 cols
        const int r0   = rowg * 2;
        const int f0   = colg * 4;
        const int rb   = blockIdx.x * 32;

        const int xrow = tid >> 3;       // 0..31
        const int xkq  = tid & 7;        // float4 along k
        const float4* xg = (const float4*)(x + (size_t)(rb + xrow) * FIN) + xkq;
        const float4* W4 = (const float4*)W;
        float4* Ws4 = (float4*)Ws;

        float4 gx, gw0, gw1;
        unsigned long long acc[4];
#pragma unroll
        for (int t = 0; t < 4; ++t) acc[t] = 0ull;

        // prologue chunk 0
        gx  = xg[0];
        gw0 = W4[tid];
        gw1 = W4[tid + 256];
        xsT[(xkq * 4 + 0) * 34 + xrow] = gx.x;
        xsT[(xkq * 4 + 1) * 34 + xrow] = gx.y;
        xsT[(xkq * 4 + 2) * 34 + xrow] = gx.z;
        xsT[(xkq * 4 + 3) * 34 + xrow] = gx.w;
        Ws4[tid]       = gw0;
        Ws4[tid + 256] = gw1;
        __syncthreads();

        for (int c = 0; c < 8; ++c) {
            if (c < 7) {
                gx  = xg[(c + 1) * 8];
                gw0 = W4[(c + 1) * 512 + tid];
                gw1 = W4[(c + 1) * 512 + tid + 256];
            }
#pragma unroll
            for (int k = 0; k < 32; ++k) {
                const float2 xv = *(const float2*)(xsT + k * 34 + r0);
                const unsigned long long xa = pack2(xv.x, xv.x);
                const unsigned long long xb = pack2(xv.y, xv.y);
                const ulonglong2 w = *(const ulonglong2*)(Ws + k * FOUT + f0);
                acc[0] = ffma2(xa, w.x, acc[0]);
                acc[1] = ffma2(xa, w.y, acc[1]);
                acc[2] = ffma2(xb, w.x, acc[2]);
                acc[3] = ffma2(xb, w.y, acc[3]);
            }
            if (c < 7) {
                __syncthreads();
                xsT[(xkq * 4 + 0) * 34 + xrow] = gx.x;
                xsT[(xkq * 4 + 1) * 34 + xrow] = gx.y;
                xsT[(xkq * 4 + 2) * 34 + xrow] = gx.z;
                xsT[(xkq * 4 + 3) * 34 + xrow] = gx.w;
                Ws4[tid]       = gw0;
                Ws4[tid + 256] = gw1;
                __syncthreads();
            }
        }

        const int rg0 = rb + r0;
        *(ulonglong2*)(g_fts + (size_t)rg0 * FOUT + f0)       = make_ulonglong2(acc[0], acc[1]);
        *(ulonglong2*)(g_fts + (size_t)(rg0 + 1) * FOUT + f0) = make_ulonglong2(acc[2], acc[3]);

        float p1r0 = 0.f, p2r0 = 0.f, p1r1 = 0.f, p2r1 = 0.f;
#pragma unroll
        for (int t = 0; t < 2; ++t) {
            const float2 v0 = unpack2(acc[t]);
            const float2 v1 = unpack2(acc[2 + t]);
            const float a1l = a1[f0 + 2 * t], a1h = a1[f0 + 2 * t + 1];
            const float a2l = a2[f0 + 2 * t], a2h = a2[f0 + 2 * t + 1];
            p1r0 += v0.x * a1l + v0.y * a1h;
            p2r0 += v0.x * a2l + v0.y * a2h;
            p1r1 += v1.x * a1l + v1.y * a1h;
            p2r1 += v1.x * a2l + v1.y * a2h;
        }
#pragma unroll
        for (int o = 1; o < 16; o <<= 1) {
            p1r0 += __shfl_xor_sync(0xffffffffu, p1r0, o);
            p2r0 += __shfl_xor_sync(0xffffffffu, p2r0, o);
            p1r1 += __shfl_xor_sync(0xffffffffu, p1r1, o);
            p2r1 += __shfl_xor_sync(0xffffffffu, p2r1, o);
        }
        if (colg == 0) {
            g_f1[rg0]     = p1r0 + b1[0];
            g_f2[rg0]     = p2r0 + b2[0];
            g_f1[rg0 + 1] = p1r1 + b1[0];
            g_f2[rg0 + 1] = p2r1 + b2[0];
        }
    } else {
        // ======== scan: pure streaming neighbor compaction ========
        const int tid0 = (blockIdx.x - PROJ_BLOCKS) * 256 + tid;   // 0..524287
        const uint4* a4 = (const uint4*)adj;
        const int STR = (NN / 4) * NN / 32;                        // 524288

#pragma unroll 1
        for (int it = 0; it < 4; ++it) {
            uint4 v[8];
#pragma unroll
            for (int k = 0; k < 8; ++k)
                v[k] = __ldcs(a4 + tid0 + (size_t)(it * 8 + k) * STR);
#pragma unroll
            for (int k = 0; k < 8; ++k) {
                unsigned m = ((~v[k].x) >> 31)
                           | (((~v[k].y) >> 31) << 1)
                           | (((~v[k].z) >> 31) << 2)
                           | (((~v[k].w) >> 31) << 3);
                if (m) {
                    const int idx = tid0 + (it * 8 + k) * STR;
                    const int row = idx >> 11;          // 2048 uint4 per row
                    const int col = (idx & 2047) * 4;
                    int base = atomicAdd(&g_cnt[row], __popc(m));
                    while (m) {
                        const int b = __ffs(m) - 1;
                        m &= m - 1;
                        if (base < CAP2) g_lst[(size_t)row * CAP2 + base] = col + b;
                        ++base;
                    }
                }
            }
        }
    }
}

// ---------------------------------------------------------------------------
// Aggregate: one block per row, 128 threads. NO sort (fp order noise ~1e-7,
// tolerance 1e-3). Score + softmax + gather fts (L2-resident) + ELU.
// Resets g_cnt for graph replay.
// ---------------------------------------------------------------------------
__global__ void __launch_bounds__(128) agg_kernel(
    const float* __restrict__ adj, const float* __restrict__ bias,
    float* __restrict__ out)
{
    __shared__ int   sj[CAP2];
    __shared__ float sp[CAP2];
    __shared__ float sred[4];
    __shared__ float sA[2][FOUT];
    __shared__ float sl[2];
    __shared__ float s_acc[FOUT];
    __shared__ float s_lsum;

    const int i   = blockIdx.x;
    const int tid = threadIdx.x;

    const int cnt = g_cnt[i];           // ALL threads read...
    __syncthreads();                    // ...before anyone resets (uniform branch!)
    if (tid == 0) g_cnt[i] = 0;         // reset for next launch/replay

    const float f1i = g_f1[i];

    if (cnt > 0 && cnt <= CAP2) {
        // load list + compute scores (no sort)
        int   j = 0;
        float s = -3.4e38f;
        if (tid < cnt) {
            j = g_lst[(size_t)i * CAP2 + tid] & (NN - 1);
            s = lrelu(f1i + g_f2[j]);
        }

        // block max
        float mx = s;
#pragma unroll
        for (int o = 16; o; o >>= 1) mx = fmaxf(mx, __shfl_xor_sync(0xffffffffu, mx, o));
        if ((tid & 31) == 0) sred[tid >> 5] = mx;
        __syncthreads();
        const float m = fmaxf(fmaxf(sred[0], sred[1]), fmaxf(sred[2], sred[3]));

        sj[tid] = j;
        sp[tid] = (tid < cnt) ? __expf(s - m) : 0.f;
        __syncthreads();

        // gather: 2 e-groups x 64 features
        const int g = tid >> 6;
        const int f = tid & 63;
        float A = 0.f, l = 0.f;
        for (int e = g; e < cnt; e += 2) {
            const float p = sp[e];
            A += p * g_fts[(size_t)sj[e] * FOUT + f];
            l += p;
        }
        sA[g][f] = A;
        if (f == 0) sl[g] = l;
        __syncthreads();

        if (tid < FOUT) {
            const float val = (sA[0][tid] + sA[1][tid]) / (sl[0] + sl[1]) + bias[tid];
            out[(size_t)i * FOUT + tid] = (val > 0.f) ? val : expm1f(val);
        }
    } else {
        // exact slow path: empty row or overflow (P ~ 1e-14)
        if (tid < FOUT) s_acc[tid] = 0.f;
        if (tid == 0)   s_lsum = 0.f;
        __syncthreads();                 // init visible before shared atomics
        const float* arow = adj + (size_t)i * NN;

        float mall = -3.4e38f;
        for (int j = tid; j < NN; j += 128)
            mall = fmaxf(mall, lrelu(f1i + g_f2[j]) + arow[j]);
#pragma unroll
        for (int o = 16; o; o >>= 1) mall = fmaxf(mall, __shfl_xor_sync(0xffffffffu, mall, o));
        if ((tid & 31) == 0) sred[tid >> 5] = mall;
        __syncthreads();
        const float m = fmaxf(fmaxf(sred[0], sred[1]), fmaxf(sred[2], sred[3]));

        float lloc = 0.f;
        for (int j = tid; j < NN; j += 128) {
            const float p = __expf(lrelu(f1i + g_f2[j]) + arow[j] - m);
            lloc += p;
            if (p > 0.f) {
                const float* fr = g_fts + (size_t)j * FOUT;
                for (int ff = 0; ff < FOUT; ++ff)
                    atomicAdd(&s_acc[ff], p * fr[ff]);
            }
        }
        atomicAdd(&s_lsum, lloc);
        __syncthreads();
        if (tid < FOUT) {
            const float val = s_acc[tid] / s_lsum + bias[tid];
            out[(size_t)i * FOUT + tid] = (val > 0.f) ? val : expm1f(val);
        }
    }
}

// ---------------------------------------------------------------------------
extern "C" void kernel_launch(void* const* d_in, const int* in_sizes, int n_in,
                              void* d_out, int out_size)
{
    (void)in_sizes; (void)n_in; (void)out_size;
    const float* x    = (const float*)d_in[0];
    const float* adj  = (const float*)d_in[1];
    const float* W    = (const float*)d_in[2];
    const float* a1   = (const float*)d_in[3];
    const float* b1   = (const float*)d_in[4];
    const float* a2   = (const float*)d_in[5];
    const float* b2   = (const float*)d_in[6];
    const float* bias = (const float*)d_in[7];
    float* out = (float*)d_out;

    fused_kernel<<<PROJ_BLOCKS + SCAN_BLOCKS, 256>>>(x, W, a1, b1, a2, b2, adj);
    agg_kernel<<<NN, 128>>>(adj, bias, out);
}

// round 7
// speedup vs baseline: 1.3328x; 1.3328x over previous
#include <cuda_runtime.h>
#include <cstdint>
#include <cstddef>

#define NN   8192
#define FIN  256
#define FOUT 64
#define CAP2 128          // per-row neighbor list capacity (mean 32, 11+ sigma safe)
#define PROJ_BLOCKS 256
#define SCAN_BLOCKS 2048  // 2048*256 threads * 32 uint4 = 8192*8192/4

__device__ float g_fts[(size_t)NN * FOUT];
__device__ float g_f1[NN];
__device__ float g_f2[NN];
__device__ int   g_cnt[NN];            // zero-init at load; reset by agg_kernel
__device__ int   g_lst[(size_t)NN * CAP2];

__device__ __forceinline__ float lrelu(float v) { return fmaxf(v, 0.2f * v); }

__device__ __forceinline__ unsigned long long pack2(float lo, float hi) {
    unsigned long long r;
    asm("mov.b64 %0, {%1, %2};" : "=l"(r) : "f"(lo), "f"(hi));
    return r;
}
__device__ __forceinline__ unsigned long long ffma2(unsigned long long a,
                                                    unsigned long long b,
                                                    unsigned long long c) {
    unsigned long long d;
    asm("fma.rn.f32x2 %0, %1, %2, %3;" : "=l"(d) : "l"(a), "l"(b), "l"(c));
    return d;
}
__device__ __forceinline__ float2 unpack2(unsigned long long v) {
    float2 f;
    asm("mov.b64 {%0, %1}, %2;" : "=f"(f.x), "=f"(f.y) : "l"(v));
    return f;
}

// ---------------------------------------------------------------------------
// Fused kernel: blocks [0, PROJ_BLOCKS) = projection GEMM (FFMA-bound),
// blocks [PROJ_BLOCKS, +SCAN_BLOCKS) = pure-streaming adjacency compaction
// (DRAM-bound). Overlapped on the chip.
// ---------------------------------------------------------------------------
__global__ void __launch_bounds__(256) fused_kernel(
    const float* __restrict__ x, const float* __restrict__ W,
    const float* __restrict__ a1, const float* __restrict__ b1,
    const float* __restrict__ a2, const float* __restrict__ b2,
    const float* __restrict__ adj)
{
    const int tid = threadIdx.x;

    if (blockIdx.x < PROJ_BLOCKS) {
        // ======== proj: 32 rows x 64 cols per block, K-chunks of 32 ========
        __shared__ __align__(16) float xsT[32 * 34];   // [k][row] pad 34
        __shared__ __align__(16) float Ws[32 * 64];    // [k][col]

        const int rowg = tid >> 4;       // 0..15 -> rows r0,r0+1
        const int colg = tid & 15;       // 0..15 -> 4 cols
        const int r0   = rowg * 2;
        const int f0   = colg * 4;
        const int rb   = blockIdx.x * 32;

        const int xrow = tid >> 3;       // 0..31
        const int xkq  = tid & 7;        // float4 along k
        const float4* xg = (const float4*)(x + (size_t)(rb + xrow) * FIN) + xkq;
        const float4* W4 = (const float4*)W;
        float4* Ws4 = (float4*)Ws;

        float4 gx, gw0, gw1;
        unsigned long long acc[4];
#pragma unroll
        for (int t = 0; t < 4; ++t) acc[t] = 0ull;

        // prologue chunk 0
        gx  = xg[0];
        gw0 = W4[tid];
        gw1 = W4[tid + 256];
        xsT[(xkq * 4 + 0) * 34 + xrow] = gx.x;
        xsT[(xkq * 4 + 1) * 34 + xrow] = gx.y;
        xsT[(xkq * 4 + 2) * 34 + xrow] = gx.z;
        xsT[(xkq * 4 + 3) * 34 + xrow] = gx.w;
        Ws4[tid]       = gw0;
        Ws4[tid + 256] = gw1;
        __syncthreads();

        for (int c = 0; c < 8; ++c) {
            if (c < 7) {
                gx  = xg[(c + 1) * 8];
                gw0 = W4[(c + 1) * 512 + tid];
                gw1 = W4[(c + 1) * 512 + tid + 256];
            }
#pragma unroll
            for (int k = 0; k < 32; ++k) {
                const float2 xv = *(const float2*)(xsT + k * 34 + r0);
                const unsigned long long xa = pack2(xv.x, xv.x);
                const unsigned long long xb = pack2(xv.y, xv.y);
                const ulonglong2 w = *(const ulonglong2*)(Ws + k * FOUT + f0);
                acc[0] = ffma2(xa, w.x, acc[0]);
                acc[1] = ffma2(xa, w.y, acc[1]);
                acc[2] = ffma2(xb, w.x, acc[2]);
                acc[3] = ffma2(xb, w.y, acc[3]);
            }
            if (c < 7) {
                __syncthreads();
                xsT[(xkq * 4 + 0) * 34 + xrow] = gx.x;
                xsT[(xkq * 4 + 1) * 34 + xrow] = gx.y;
                xsT[(xkq * 4 + 2) * 34 + xrow] = gx.z;
                xsT[(xkq * 4 + 3) * 34 + xrow] = gx.w;
                Ws4[tid]       = gw0;
                Ws4[tid + 256] = gw1;
                __syncthreads();
            }
        }

        const int rg0 = rb + r0;
        *(ulonglong2*)(g_fts + (size_t)rg0 * FOUT + f0)       = make_ulonglong2(acc[0], acc[1]);
        *(ulonglong2*)(g_fts + (size_t)(rg0 + 1) * FOUT + f0) = make_ulonglong2(acc[2], acc[3]);

        float p1r0 = 0.f, p2r0 = 0.f, p1r1 = 0.f, p2r1 = 0.f;
#pragma unroll
        for (int t = 0; t < 2; ++t) {
            const float2 v0 = unpack2(acc[t]);
            const float2 v1 = unpack2(acc[2 + t]);
            const float a1l = a1[f0 + 2 * t], a1h = a1[f0 + 2 * t + 1];
            const float a2l = a2[f0 + 2 * t], a2h = a2[f0 + 2 * t + 1];
            p1r0 += v0.x * a1l + v0.y * a1h;
            p2r0 += v0.x * a2l + v0.y * a2h;
            p1r1 += v1.x * a1l + v1.y * a1h;
            p2r1 += v1.x * a2l + v1.y * a2h;
        }
#pragma unroll
        for (int o = 1; o < 16; o <<= 1) {
            p1r0 += __shfl_xor_sync(0xffffffffu, p1r0, o);
            p2r0 += __shfl_xor_sync(0xffffffffu, p2r0, o);
            p1r1 += __shfl_xor_sync(0xffffffffu, p1r1, o);
            p2r1 += __shfl_xor_sync(0xffffffffu, p2r1, o);
        }
        if (colg == 0) {
            g_f1[rg0]     = p1r0 + b1[0];
            g_f2[rg0]     = p2r0 + b2[0];
            g_f1[rg0 + 1] = p1r1 + b1[0];
            g_f2[rg0 + 1] = p2r1 + b2[0];
        }
    } else {
        // ======== scan: pure streaming neighbor compaction ========
        const int tid0 = (blockIdx.x - PROJ_BLOCKS) * 256 + tid;   // 0..524287
        const uint4* a4 = (const uint4*)adj;
        const int STR = (NN / 4) * NN / 32;                        // 524288

#pragma unroll 1
        for (int it = 0; it < 4; ++it) {
            uint4 v[8];
#pragma unroll
            for (int k = 0; k < 8; ++k)
                v[k] = __ldcs(a4 + tid0 + (size_t)(it * 8 + k) * STR);
#pragma unroll
            for (int k = 0; k < 8; ++k) {
                unsigned m = ((~v[k].x) >> 31)
                           | (((~v[k].y) >> 31) << 1)
                           | (((~v[k].z) >> 31) << 2)
                           | (((~v[k].w) >> 31) << 3);
                if (m) {
                    const int idx = tid0 + (it * 8 + k) * STR;
                    const int row = idx >> 11;          // 2048 uint4 per row
                    const int col = (idx & 2047) * 4;
                    int base = atomicAdd(&g_cnt[row], __popc(m));
                    while (m) {
                        const int b = __ffs(m) - 1;
                        m &= m - 1;
                        if (base < CAP2) g_lst[(size_t)row * CAP2 + base] = col + b;
                        ++base;
                    }
                }
            }
        }
    }
}

// ---------------------------------------------------------------------------
// Aggregate: ONE WARP PER ROW (8 rows / 256-thread block, grid=1024, single
// wave). No block barriers. List + scores + softmax in registers; gather is a
// statically-unrolled 32-wide loop (padded entries have p=0), giving deep
// LDG pipelining. Each lane owns 2 output features. Resets g_cnt for replay.
// ---------------------------------------------------------------------------
__global__ void __launch_bounds__(256) agg_kernel(
    const float* __restrict__ adj, const float* __restrict__ bias,
    float* __restrict__ out)
{
    const int tid  = threadIdx.x;
    const int wid  = tid >> 5;
    const int lane = tid & 31;
    const int i    = blockIdx.x * 8 + wid;

    const int cnt = g_cnt[i];           // whole warp reads (1 transaction)...
    if (lane == 0) g_cnt[i] = 0;        // ...store after load in program order

    const float  f1i = g_f1[i];
    const float2 bv  = *(const float2*)(bias + 2 * lane);

    if (cnt > 0 && cnt <= CAP2) {
        // ---- fast path: list/scores in 4 regs per lane ----
        int   jj[4];
        float ss[4];
#pragma unroll
        for (int t = 0; t < 4; ++t) {
            const int e = lane + 32 * t;
            if (e < cnt) {
                jj[t] = g_lst[(size_t)i * CAP2 + e] & (NN - 1);
                ss[t] = lrelu(f1i + g_f2[jj[t]]);
            } else {
                jj[t] = 0;
                ss[t] = -3.4e38f;
            }
        }

        float m = fmaxf(fmaxf(ss[0], ss[1]), fmaxf(ss[2], ss[3]));
#pragma unroll
        for (int o = 16; o; o >>= 1) m = fmaxf(m, __shfl_xor_sync(0xffffffffu, m, o));

        float pp[4];
        float l = 0.f;
#pragma unroll
        for (int t = 0; t < 4; ++t) {
            pp[t] = (lane + 32 * t < cnt) ? __expf(ss[t] - m) : 0.f;
            l += pp[t];
        }
#pragma unroll
        for (int o = 16; o; o >>= 1) l += __shfl_xor_sync(0xffffffffu, l, o);

        // ---- gather: static 32-wide unroll per register group ----
        float A0 = 0.f, A1 = 0.f;
#pragma unroll
        for (int t = 0; t < 4; ++t) {
            if (cnt > 32 * t) {
#pragma unroll
                for (int src = 0; src < 32; ++src) {
                    const float pe = __shfl_sync(0xffffffffu, pp[t], src);
                    const int   je = __shfl_sync(0xffffffffu, jj[t], src);
                    const float2 fv = *(const float2*)(g_fts + (size_t)je * FOUT + 2 * lane);
                    A0 += pe * fv.x;
                    A1 += pe * fv.y;
                }
            }
        }

        const float inv = 1.f / l;
        const float v0 = A0 * inv + bv.x;
        const float v1 = A1 * inv + bv.y;
        float2 ov;
        ov.x = (v0 > 0.f) ? v0 : expm1f(v0);
        ov.y = (v1 > 0.f) ? v1 : expm1f(v1);
        *(float2*)(out + (size_t)i * FOUT + 2 * lane) = ov;
    } else {
        // ---- exact slow path (empty row / overflow; P ~ 1e-14), warp-local ----
        const float* arow = adj + (size_t)i * NN;

        float m = -3.4e38f;
        for (int j = lane; j < NN; j += 32)
            m = fmaxf(m, lrelu(f1i + g_f2[j]) + arow[j]);
#pragma unroll
        for (int o = 16; o; o >>= 1) m = fmaxf(m, __shfl_xor_sync(0xffffffffu, m, o));

        float A0 = 0.f, A1 = 0.f, l = 0.f;
        for (int j0 = 0; j0 < NN; j0 += 32) {
            const float p = __expf(lrelu(f1i + g_f2[j0 + lane]) + arow[j0 + lane] - m);
            l += p;
#pragma unroll 1
            for (int src = 0; src < 32; ++src) {
                const float pe = __shfl_sync(0xffffffffu, p, src);
                if (pe > 0.f) {
                    const float2 fv = *(const float2*)(g_fts + (size_t)(j0 + src) * FOUT + 2 * lane);
                    A0 += pe * fv.x;
                    A1 += pe * fv.y;
                }
            }
        }
#pragma unroll
        for (int o = 16; o; o >>= 1) l += __shfl_xor_sync(0xffffffffu, l, o);

        const float v0 = A0 / l + bv.x;
        const float v1 = A1 / l + bv.y;
        float2 ov;
        ov.x = (v0 > 0.f) ? v0 : expm1f(v0);
        ov.y = (v1 > 0.f) ? v1 : expm1f(v1);
        *(float2*)(out + (size_t)i * FOUT + 2 * lane) = ov;
    }
}

// ---------------------------------------------------------------------------
extern "C" void kernel_launch(void* const* d_in, const int* in_sizes, int n_in,
                              void* d_out, int out_size)
{
    (void)in_sizes; (void)n_in; (void)out_size;
    const float* x    = (const float*)d_in[0];
    const float* adj  = (const float*)d_in[1];
    const float* W    = (const float*)d_in[2];
    const float* a1   = (const float*)d_in[3];
    const float* b1   = (const float*)d_in[4];
    const float* a2   = (const float*)d_in[5];
    const float* b2   = (const float*)d_in[6];
    const float* bias = (const float*)d_in[7];
    float* out = (float*)d_out;

    fused_kernel<<<PROJ_BLOCKS + SCAN_BLOCKS, 256>>>(x, W, a1, b1, a2, b2, adj);
    agg_kernel<<<NN / 8, 256>>>(adj, bias, out);
}